// round 13
// baseline (speedup 1.0000x reference)
#include <cuda_runtime.h>
#include <cuda_fp16.h>
#include <cstdint>

#define N_MAX 100000
#define E_MAX 1000000
#define D 64
#define D4 16               // D/4 float4 per row
#define TILE_ROWS 128       // gemm2 tile
#define TR2 64              // hetero gemm tile (small smem, 62-reg body)
#define SCAN_B 1024

// Scratch (static device globals — no allocations allowed)
__device__ int    g_deg     [N_MAX];
__device__ int    g_rowptr  [N_MAX + 1];
__device__ int    g_cursor  [N_MAX];
__device__ int    g_srcsort [E_MAX];
__device__ int    g_bsums   [128];
__device__ float  s_dinv    [N_MAX];
__device__ uint4  s_h       [N_MAX * 8];    // fp16 gather source: 64 halves/row
__device__ uint4  s_yh      [N_MAX * 8];    // layer-1 output, fp16

// ---------------------------------------------------------------------------
// edge_index is INT32 on device (JAX x64 disabled canonicalizes int64->int32).
__global__ void hist_kernel(const int* __restrict__ ei, int E) {
    int e = blockIdx.x * blockDim.x + threadIdx.x;
    if (e < E) atomicAdd(&g_deg[ei[E + e]], 1);
}

// exclusive scan, stage 1: shuffle-based per-block scan + block totals
__global__ __launch_bounds__(SCAN_B) void scan_local_kernel(int n) {
    __shared__ int wsums[32];
    int t = threadIdx.x, lane = t & 31, w = t >> 5;
    int i = blockIdx.x * SCAN_B + t;
    int orig = (i < n) ? g_deg[i] : 0;
    int v = orig;
    #pragma unroll
    for (int o = 1; o < 32; o <<= 1) {
        int u = __shfl_up_sync(0xffffffffu, v, o);
        if (lane >= o) v += u;
    }
    if (lane == 31) wsums[w] = v;
    __syncthreads();
    if (w == 0) {
        int s = wsums[lane];
        #pragma unroll
        for (int o = 1; o < 32; o <<= 1) {
            int u = __shfl_up_sync(0xffffffffu, s, o);
            if (lane >= o) s += u;
        }
        wsums[lane] = s;
    }
    __syncthreads();
    int incl = v + ((w > 0) ? wsums[w - 1] : 0);
    if (i < n) g_rowptr[i] = incl - orig;             // exclusive
    if (t == SCAN_B - 1) g_bsums[blockIdx.x] = incl;  // block total
}

// stage 2 (fused): per-block redundant reduction of lower block sums; dinv; cursors.
__global__ __launch_bounds__(SCAN_B) void scan_add_fused_kernel(int n, int E, int nb) {
    __shared__ int sh[128];
    __shared__ int offset;
    int t = threadIdx.x;
    if (t < 128) sh[t] = (t < nb && t < (int)blockIdx.x) ? g_bsums[t] : 0;
    __syncthreads();
    if (t < 64) sh[t] += sh[t + 64];
    __syncthreads();
    if (t < 32) {
        int v = sh[t] + sh[t + 32];
        #pragma unroll
        for (int o = 16; o > 0; o >>= 1) v += __shfl_down_sync(0xffffffffu, v, o);
        if (t == 0) offset = v;
    }
    __syncthreads();
    int i = blockIdx.x * SCAN_B + t;
    if (i < n) {
        int r = g_rowptr[i] + offset;
        g_rowptr[i] = r;
        g_cursor[i] = r;
        s_dinv[i] = rsqrtf((float)g_deg[i] + 1.0f);   // +1 self loop
    }
    if (i == 0) g_rowptr[n] = E;
}

// ---------------------------------------------------------------------------
// fp16 store helper
__device__ __forceinline__ void store_row_fp16(
    int row, int cg, float a0, float a1, float a2, float a3)
{
    float dv = s_dinv[row];
    __half2 p0 = __floats2half2_rn(a0 * dv, a1 * dv);
    __half2 p1 = __floats2half2_rn(a2 * dv, a3 * dv);
    uint2 u;
    u.x = *(unsigned int*)&p0;
    u.y = *(unsigned int*)&p1;
    ((uint2*)s_h)[row * 16 + cg] = u;
}

// ---------------------------------------------------------------------------
// TRUE-interleaved heterogeneous launch (R11-proven, 109.1us config): in every
// group of (R+1) consecutive blocks, R run counting-sort and 1 runs a GEMM1
// tile. Lean fp32 TR2=64 gemm body; launch_bounds caps regs at 64.
__global__ __launch_bounds__(256, 4) void sort_gemm1_kernel(
    const float* __restrict__ X, const float* __restrict__ W,
    const int* __restrict__ ei, int n, int E, int R)
{
    __shared__ float4 ws[D * D4];     // 16KB
    __shared__ float4 xs[TR2 * D4];   // 16KB

    int g = blockIdx.x / (R + 1);
    int r = blockIdx.x % (R + 1);

    if (r != R) {
        // ---- counting-sort scatter ----
        int e = (g * R + r) * 256 + threadIdx.x;
        if (e < E) {
            int src = ei[e];
            int dst = ei[E + e];
            int pos = atomicAdd(&g_cursor[dst], 1);
            g_srcsort[pos] = src;
        }
        return;
    }

    // ---- GEMM1: h = dinv * (X @ W1), fp16 store ----
    const int tid  = threadIdx.x;
    const int row0 = g * TR2;
    if (row0 >= n) return;

    const float4* W4 = (const float4*)W;
    #pragma unroll
    for (int i = tid; i < D * D4; i += 256) ws[i] = __ldg(&W4[i]);

    const float4* X4 = (const float4*)X;
    #pragma unroll
    for (int i = tid; i < TR2 * D4; i += 256) {
        int rr = i >> 4;
        float4 v = make_float4(0.f, 0.f, 0.f, 0.f);
        if (row0 + rr < n) v = __ldg(&X4[(row0 + rr) * D4 + (i & 15)]);
        xs[i] = v;
    }
    __syncthreads();

    const int cg = tid & 15;
    const int rg = tid >> 4;   // 4 rows each

    float acc[4][4];
    #pragma unroll
    for (int rr = 0; rr < 4; rr++)
        #pragma unroll
        for (int c = 0; c < 4; c++) acc[rr][c] = 0.f;

    #pragma unroll 2
    for (int k = 0; k < D; k += 4) {
        float4 w0 = ws[(k + 0) * D4 + cg];
        float4 w1 = ws[(k + 1) * D4 + cg];
        float4 w2 = ws[(k + 2) * D4 + cg];
        float4 w3 = ws[(k + 3) * D4 + cg];
        #pragma unroll
        for (int rr = 0; rr < 4; rr++) {
            float4 xv = xs[(rg * 4 + rr) * D4 + (k >> 2)];
            acc[rr][0] += xv.x * w0.x + xv.y * w1.x + xv.z * w2.x + xv.w * w3.x;
            acc[rr][1] += xv.x * w0.y + xv.y * w1.y + xv.z * w2.y + xv.w * w3.y;
            acc[rr][2] += xv.x * w0.z + xv.y * w1.z + xv.z * w2.z + xv.w * w3.z;
            acc[rr][3] += xv.x * w0.w + xv.y * w1.w + xv.z * w2.w + xv.w * w3.w;
        }
    }

    #pragma unroll
    for (int rr = 0; rr < 4; rr++) {
        int row = row0 + rg * 4 + rr;
        if (row < n)
            store_row_fp16(row, cg, acc[rr][0], acc[rr][1], acc[rr][2], acc[rr][3]);
    }
}

// ---------------------------------------------------------------------------
// layer-2 GEMM: reads fp16 y (16KB xs tile -> 32KB smem total, 128-row tile)
__global__ __launch_bounds__(256) void gemm2_kernel(
    const float* __restrict__ W, int n)
{
    __shared__ float4 ws[D * D4];            // 16KB
    __shared__ uint2  xs2[TILE_ROWS * D4];   // 16KB

    const int tid  = threadIdx.x;
    const int row0 = blockIdx.x * TILE_ROWS;

    const float4* W4 = (const float4*)W;
    #pragma unroll
    for (int i = tid; i < D * D4; i += 256) ws[i] = __ldg(&W4[i]);

    const uint2* Y2 = (const uint2*)s_yh;
    #pragma unroll
    for (int i = tid; i < TILE_ROWS * D4; i += 256) {
        int rr = i >> 4;
        uint2 u = make_uint2(0u, 0u);
        if (row0 + rr < n) u = __ldg(&Y2[(row0 + rr) * 16 + (i & 15)]);
        xs2[i] = u;
    }
    __syncthreads();

    const int cg = tid & 15;
    const int rg = tid >> 4;   // 8 rows each

    float acc[8][4];
    #pragma unroll
    for (int r = 0; r < 8; r++)
        #pragma unroll
        for (int c = 0; c < 4; c++) acc[r][c] = 0.f;

    #pragma unroll 2
    for (int k = 0; k < D; k += 4) {
        float4 w0 = ws[(k + 0) * D4 + cg];
        float4 w1 = ws[(k + 1) * D4 + cg];
        float4 w2 = ws[(k + 2) * D4 + cg];
        float4 w3 = ws[(k + 3) * D4 + cg];
        #pragma unroll
        for (int r = 0; r < 8; r++) {
            uint2 xu = xs2[(rg * 8 + r) * D4 + (k >> 2)];
            float2 xa = __half22float2(*(__half2*)&xu.x);
            float2 xb = __half22float2(*(__half2*)&xu.y);
            acc[r][0] += xa.x * w0.x + xa.y * w1.x + xb.x * w2.x + xb.y * w3.x;
            acc[r][1] += xa.x * w0.y + xa.y * w1.y + xb.x * w2.y + xb.y * w3.y;
            acc[r][2] += xa.x * w0.z + xa.y * w1.z + xb.x * w2.z + xb.y * w3.z;
            acc[r][3] += xa.x * w0.w + xa.y * w1.w + xb.x * w2.w + xb.y * w3.w;
        }
    }

    #pragma unroll
    for (int r = 0; r < 8; r++) {
        int row = row0 + rg * 8 + r;
        if (row < n)
            store_row_fp16(row, cg, acc[r][0], acc[r][1], acc[r][2], acc[r][3]);
    }
}

// ---------------------------------------------------------------------------
__device__ __forceinline__ void acc_add8(float acc[8], uint4 u) {
    float2 f0 = __half22float2(*(__half2*)&u.x);
    float2 f1 = __half22float2(*(__half2*)&u.y);
    float2 f2 = __half22float2(*(__half2*)&u.z);
    float2 f3 = __half22float2(*(__half2*)&u.w);
    acc[0] += f0.x; acc[1] += f0.y; acc[2] += f1.x; acc[3] += f1.y;
    acc[4] += f2.x; acc[5] += f2.y; acc[6] += f3.x; acc[7] += f3.y;
}

// Gather-aggregate + epilogue, ONE WARP PER NODE: 4 subgroups of 8 lanes take
// every-4th edge (intra-warp balanced at ceil(deg/4) — removes the max-of-4-
// nodes divergence of the 8-thread/node layout), then 2 shfl_down rounds
// reduce across subgroups. lanes 0-7 apply bias/relu and store.
// OUT_HALF: write fp16 (layer-1 -> s_yh); else fp32 (final output).
template <bool OUT_HALF>
__global__ __launch_bounds__(256) void aggregate_kernel(
    const float* __restrict__ b, void* __restrict__ out, int n)
{
    int idx  = blockIdx.x * blockDim.x + threadIdx.x;
    int v    = idx >> 5;           // warp-uniform node id
    if (v >= n) return;
    int lane = threadIdx.x & 31;
    int j    = lane & 7;           // column group (8 halves)
    int sub  = lane >> 3;          // subgroup 0..3

    float acc[8];
    #pragma unroll
    for (int c = 0; c < 8; c++) acc[c] = 0.f;

    int beg = __ldg(&g_rowptr[v]);
    int end = __ldg(&g_rowptr[v + 1]);

    for (int k = beg + sub; k < end; k += 4) {
        int s = __ldg(&g_srcsort[k]);
        acc_add8(acc, __ldg(&s_h[s * 8 + j]));
    }

    // reduce across the 4 subgroups -> totals land in lanes 0-7
    #pragma unroll
    for (int c = 0; c < 8; c++) {
        acc[c] += __shfl_down_sync(0xffffffffu, acc[c], 16);
        acc[c] += __shfl_down_sync(0xffffffffu, acc[c], 8);
    }

    if (sub == 0) {
        acc_add8(acc, __ldg(&s_h[v * 8 + j]));         // self loop

        float dv = __ldg(&s_dinv[v]);
        const float4* b4 = (const float4*)b;
        float4 bb0 = __ldg(&b4[j * 2 + 0]);
        float4 bb1 = __ldg(&b4[j * 2 + 1]);
        float o[8];
        o[0] = fmaxf(fmaf(acc[0], dv, bb0.x), 0.f);
        o[1] = fmaxf(fmaf(acc[1], dv, bb0.y), 0.f);
        o[2] = fmaxf(fmaf(acc[2], dv, bb0.z), 0.f);
        o[3] = fmaxf(fmaf(acc[3], dv, bb0.w), 0.f);
        o[4] = fmaxf(fmaf(acc[4], dv, bb1.x), 0.f);
        o[5] = fmaxf(fmaf(acc[5], dv, bb1.y), 0.f);
        o[6] = fmaxf(fmaf(acc[6], dv, bb1.z), 0.f);
        o[7] = fmaxf(fmaf(acc[7], dv, bb1.w), 0.f);

        if (OUT_HALF) {
            __half2 p0 = __floats2half2_rn(o[0], o[1]);
            __half2 p1 = __floats2half2_rn(o[2], o[3]);
            __half2 p2 = __floats2half2_rn(o[4], o[5]);
            __half2 p3 = __floats2half2_rn(o[6], o[7]);
            uint4 u;
            u.x = *(unsigned int*)&p0;
            u.y = *(unsigned int*)&p1;
            u.z = *(unsigned int*)&p2;
            u.w = *(unsigned int*)&p3;
            ((uint4*)out)[v * 8 + j] = u;
        } else {
            float4* O4 = (float4*)out;
            O4[v * 16 + j * 2 + 0] = make_float4(o[0], o[1], o[2], o[3]);
            O4[v * 16 + j * 2 + 1] = make_float4(o[4], o[5], o[6], o[7]);
        }
    }
}

// ---------------------------------------------------------------------------
extern "C" void kernel_launch(void* const* d_in, const int* in_sizes, int n_in,
                              void* d_out, int out_size)
{
    const float* x  = (const float*)d_in[0];
    const int*   ei = (const int*)d_in[1];      // int32 (JAX x64 disabled)
    const float* W1 = (const float*)d_in[2];
    const float* b1 = (const float*)d_in[3];
    const float* W2 = (const float*)d_in[4];
    const float* b2 = (const float*)d_in[5];

    const int n = in_sizes[0] / D;        // 100000
    const int E = in_sizes[1] / 2;        // 1000000

    const int nb_e    = (E + 255) / 256;                   // sort blocks needed
    const int nb_sc   = (n + SCAN_B - 1) / SCAN_B;
    const int nb_gmm  = (n + TILE_ROWS - 1) / TILE_ROWS;   // gemm2 tiles
    const int nb_gmm1 = (n + TR2 - 1) / TR2;               // gemm1 tiles
    const int nb_agg  = (n + 7) / 8;                       // 8 nodes (warps) / block
    const int R       = (nb_e + nb_gmm1 - 1) / nb_gmm1;    // sort : gemm ratio

    // zero degree counters via a graph memset node
    void* degp = nullptr;
    cudaGetSymbolAddress(&degp, g_deg);
    cudaMemsetAsync(degp, 0, (size_t)n * sizeof(int));

    void* yh = nullptr;
    cudaGetSymbolAddress(&yh, s_yh);

    // --- graph preprocessing ---
    hist_kernel<<<nb_e, 256>>>(ei, E);
    scan_local_kernel<<<nb_sc, SCAN_B>>>(n);
    scan_add_fused_kernel<<<nb_sc, SCAN_B>>>(n, E, nb_sc);

    // sort truly interleaved with GEMM1 (R sort : 1 gemm per group, per wave)
    sort_gemm1_kernel<<<nb_gmm1 * (R + 1), 256>>>(x, W1, ei, n, E, R);

    // layer 1 aggregation -> fp16 y
    aggregate_kernel<true><<<nb_agg, 256>>>(b1, yh, n);

    // layer 2
    gemm2_kernel<<<nb_gmm, 256>>>(W2, n);
    aggregate_kernel<false><<<nb_agg, 256>>>(b2, d_out, n);
}

// round 14
// speedup vs baseline: 1.1413x; 1.1413x over previous
#include <cuda_runtime.h>
#include <cuda_fp16.h>
#include <cstdint>

#define N_MAX 100000
#define E_MAX 1000000
#define D 64
#define D4 16               // D/4 float4 per row
#define TILE_ROWS 128       // gemm2 tile
#define TR2 32              // hetero gemm tile (20KB smem, ~40-reg body)
#define SCAN_B 1024

// Scratch (static device globals — no allocations allowed)
__device__ int    g_deg     [N_MAX];
__device__ int    g_rowptr  [N_MAX + 1];
__device__ int    g_cursor  [N_MAX];
__device__ int    g_srcsort [E_MAX];
__device__ int    g_bsums   [128];
__device__ float  s_dinv    [N_MAX];
__device__ uint4  s_h       [N_MAX * 8];    // fp16 gather source: 64 halves/row
__device__ uint4  s_yh      [N_MAX * 8];    // layer-1 output, fp16

// ---------------------------------------------------------------------------
// edge_index is INT32 on device (JAX x64 disabled canonicalizes int64->int32).
__global__ void hist_kernel(const int* __restrict__ ei, int E) {
    int e = blockIdx.x * blockDim.x + threadIdx.x;
    if (e < E) atomicAdd(&g_deg[ei[E + e]], 1);
}

// exclusive scan, stage 1: shuffle-based per-block scan + block totals
__global__ __launch_bounds__(SCAN_B) void scan_local_kernel(int n) {
    __shared__ int wsums[32];
    int t = threadIdx.x, lane = t & 31, w = t >> 5;
    int i = blockIdx.x * SCAN_B + t;
    int orig = (i < n) ? g_deg[i] : 0;
    int v = orig;
    #pragma unroll
    for (int o = 1; o < 32; o <<= 1) {
        int u = __shfl_up_sync(0xffffffffu, v, o);
        if (lane >= o) v += u;
    }
    if (lane == 31) wsums[w] = v;
    __syncthreads();
    if (w == 0) {
        int s = wsums[lane];
        #pragma unroll
        for (int o = 1; o < 32; o <<= 1) {
            int u = __shfl_up_sync(0xffffffffu, s, o);
            if (lane >= o) s += u;
        }
        wsums[lane] = s;
    }
    __syncthreads();
    int incl = v + ((w > 0) ? wsums[w - 1] : 0);
    if (i < n) g_rowptr[i] = incl - orig;             // exclusive
    if (t == SCAN_B - 1) g_bsums[blockIdx.x] = incl;  // block total
}

// stage 2 (fused): per-block redundant reduction of lower block sums; dinv; cursors.
__global__ __launch_bounds__(SCAN_B) void scan_add_fused_kernel(int n, int E, int nb) {
    __shared__ int sh[128];
    __shared__ int offset;
    int t = threadIdx.x;
    if (t < 128) sh[t] = (t < nb && t < (int)blockIdx.x) ? g_bsums[t] : 0;
    __syncthreads();
    if (t < 64) sh[t] += sh[t + 64];
    __syncthreads();
    if (t < 32) {
        int v = sh[t] + sh[t + 32];
        #pragma unroll
        for (int o = 16; o > 0; o >>= 1) v += __shfl_down_sync(0xffffffffu, v, o);
        if (t == 0) offset = v;
    }
    __syncthreads();
    int i = blockIdx.x * SCAN_B + t;
    if (i < n) {
        int r = g_rowptr[i] + offset;
        g_rowptr[i] = r;
        g_cursor[i] = r;
        s_dinv[i] = rsqrtf((float)g_deg[i] + 1.0f);   // +1 self loop
    }
    if (i == 0) g_rowptr[n] = E;
}

// ---------------------------------------------------------------------------
// fp16 store helper
__device__ __forceinline__ void store_row_fp16(
    int row, int cg, float a0, float a1, float a2, float a3)
{
    float dv = s_dinv[row];
    __half2 p0 = __floats2half2_rn(a0 * dv, a1 * dv);
    __half2 p1 = __floats2half2_rn(a2 * dv, a3 * dv);
    uint2 u;
    u.x = *(unsigned int*)&p0;
    u.y = *(unsigned int*)&p1;
    ((uint2*)s_h)[row * 16 + cg] = u;
}

// ---------------------------------------------------------------------------
// TRUE-interleaved heterogeneous launch: per group of (R+1) consecutive
// blocks, R run counting-sort, 1 runs a GEMM1 tile. TR2=32 tile (20KB smem)
// + launch_bounds(256,6) caps regs at ~42 -> 6 blocks/SM = 75% occupancy,
// matching the standalone sort's operating point (sort is latency-bound:
// throughput ~ resident warps).
__global__ __launch_bounds__(256, 6) void sort_gemm1_kernel(
    const float* __restrict__ X, const float* __restrict__ W,
    const int* __restrict__ ei, int n, int E, int R)
{
    __shared__ float4 ws[D * D4];     // 16KB
    __shared__ float4 xs[TR2 * D4];   // 4KB

    int g = blockIdx.x / (R + 1);
    int r = blockIdx.x % (R + 1);

    if (r != R) {
        // ---- counting-sort scatter ----
        int e = (g * R + r) * 256 + threadIdx.x;
        if (e < E) {
            int src = ei[e];
            int dst = ei[E + e];
            int pos = atomicAdd(&g_cursor[dst], 1);
            g_srcsort[pos] = src;
        }
        return;
    }

    // ---- GEMM1: h = dinv * (X @ W1), fp16 store ----
    const int tid  = threadIdx.x;
    const int row0 = g * TR2;
    if (row0 >= n) return;

    const float4* W4 = (const float4*)W;
    #pragma unroll
    for (int i = tid; i < D * D4; i += 256) ws[i] = __ldg(&W4[i]);

    const float4* X4 = (const float4*)X;
    #pragma unroll
    for (int i = tid; i < TR2 * D4; i += 256) {
        int rr = i >> 4;
        float4 v = make_float4(0.f, 0.f, 0.f, 0.f);
        if (row0 + rr < n) v = __ldg(&X4[(row0 + rr) * D4 + (i & 15)]);
        xs[i] = v;
    }
    __syncthreads();

    const int cg = tid & 15;
    const int rg = tid >> 4;   // 2 rows each

    float acc[2][4];
    #pragma unroll
    for (int rr = 0; rr < 2; rr++)
        #pragma unroll
        for (int c = 0; c < 4; c++) acc[rr][c] = 0.f;

    #pragma unroll 2
    for (int k = 0; k < D; k += 4) {
        float4 w0 = ws[(k + 0) * D4 + cg];
        float4 w1 = ws[(k + 1) * D4 + cg];
        float4 w2 = ws[(k + 2) * D4 + cg];
        float4 w3 = ws[(k + 3) * D4 + cg];
        #pragma unroll
        for (int rr = 0; rr < 2; rr++) {
            float4 xv = xs[(rg * 2 + rr) * D4 + (k >> 2)];
            acc[rr][0] += xv.x * w0.x + xv.y * w1.x + xv.z * w2.x + xv.w * w3.x;
            acc[rr][1] += xv.x * w0.y + xv.y * w1.y + xv.z * w2.y + xv.w * w3.y;
            acc[rr][2] += xv.x * w0.z + xv.y * w1.z + xv.z * w2.z + xv.w * w3.z;
            acc[rr][3] += xv.x * w0.w + xv.y * w1.w + xv.z * w2.w + xv.w * w3.w;
        }
    }

    #pragma unroll
    for (int rr = 0; rr < 2; rr++) {
        int row = row0 + rg * 2 + rr;
        if (row < n)
            store_row_fp16(row, cg, acc[rr][0], acc[rr][1], acc[rr][2], acc[rr][3]);
    }
}

// ---------------------------------------------------------------------------
// layer-2 GEMM: reads fp16 y (16KB xs tile -> 32KB smem total, 128-row tile)
__global__ __launch_bounds__(256) void gemm2_kernel(
    const float* __restrict__ W, int n)
{
    __shared__ float4 ws[D * D4];            // 16KB
    __shared__ uint2  xs2[TILE_ROWS * D4];   // 16KB

    const int tid  = threadIdx.x;
    const int row0 = blockIdx.x * TILE_ROWS;

    const float4* W4 = (const float4*)W;
    #pragma unroll
    for (int i = tid; i < D * D4; i += 256) ws[i] = __ldg(&W4[i]);

    const uint2* Y2 = (const uint2*)s_yh;
    #pragma unroll
    for (int i = tid; i < TILE_ROWS * D4; i += 256) {
        int rr = i >> 4;
        uint2 u = make_uint2(0u, 0u);
        if (row0 + rr < n) u = __ldg(&Y2[(row0 + rr) * 16 + (i & 15)]);
        xs2[i] = u;
    }
    __syncthreads();

    const int cg = tid & 15;
    const int rg = tid >> 4;   // 8 rows each

    float acc[8][4];
    #pragma unroll
    for (int r = 0; r < 8; r++)
        #pragma unroll
        for (int c = 0; c < 4; c++) acc[r][c] = 0.f;

    #pragma unroll 2
    for (int k = 0; k < D; k += 4) {
        float4 w0 = ws[(k + 0) * D4 + cg];
        float4 w1 = ws[(k + 1) * D4 + cg];
        float4 w2 = ws[(k + 2) * D4 + cg];
        float4 w3 = ws[(k + 3) * D4 + cg];
        #pragma unroll
        for (int r = 0; r < 8; r++) {
            uint2 xu = xs2[(rg * 8 + r) * D4 + (k >> 2)];
            float2 xa = __half22float2(*(__half2*)&xu.x);
            float2 xb = __half22float2(*(__half2*)&xu.y);
            acc[r][0] += xa.x * w0.x + xa.y * w1.x + xb.x * w2.x + xb.y * w3.x;
            acc[r][1] += xa.x * w0.y + xa.y * w1.y + xb.x * w2.y + xb.y * w3.y;
            acc[r][2] += xa.x * w0.z + xa.y * w1.z + xb.x * w2.z + xb.y * w3.z;
            acc[r][3] += xa.x * w0.w + xa.y * w1.w + xb.x * w2.w + xb.y * w3.w;
        }
    }

    #pragma unroll
    for (int r = 0; r < 8; r++) {
        int row = row0 + rg * 8 + r;
        if (row < n)
            store_row_fp16(row, cg, acc[r][0], acc[r][1], acc[r][2], acc[r][3]);
    }
}

// ---------------------------------------------------------------------------
__device__ __forceinline__ void acc_add8(float acc[8], uint4 u) {
    float2 f0 = __half22float2(*(__half2*)&u.x);
    float2 f1 = __half22float2(*(__half2*)&u.y);
    float2 f2 = __half22float2(*(__half2*)&u.z);
    float2 f3 = __half22float2(*(__half2*)&u.w);
    acc[0] += f0.x; acc[1] += f0.y; acc[2] += f1.x; acc[3] += f1.y;
    acc[4] += f2.x; acc[5] += f2.y; acc[6] += f3.x; acc[7] += f3.y;
}

// Gather-aggregate + epilogue (R11-proven form). 8 threads/node, one uint4
// (8 halves) each, batch-4 index loads for MLP.
// OUT_HALF: write fp16 (layer-1 -> s_yh); else fp32 (final output).
template <bool OUT_HALF>
__global__ __launch_bounds__(256) void aggregate_kernel(
    const float* __restrict__ b, void* __restrict__ out, int n)
{
    int idx = blockIdx.x * blockDim.x + threadIdx.x;
    int v = idx >> 3;
    if (v >= n) return;
    int j = idx & 7;

    float acc[8];
    #pragma unroll
    for (int c = 0; c < 8; c++) acc[c] = 0.f;
    acc_add8(acc, __ldg(&s_h[v * 8 + j]));             // self loop

    int beg = __ldg(&g_rowptr[v]);
    int end = __ldg(&g_rowptr[v + 1]);

    int k = beg;
    #pragma unroll 1
    for (; k + 4 <= end; k += 4) {
        int s0 = __ldg(&g_srcsort[k + 0]);
        int s1 = __ldg(&g_srcsort[k + 1]);
        int s2 = __ldg(&g_srcsort[k + 2]);
        int s3 = __ldg(&g_srcsort[k + 3]);
        uint4 u0 = __ldg(&s_h[s0 * 8 + j]);
        uint4 u1 = __ldg(&s_h[s1 * 8 + j]);
        uint4 u2 = __ldg(&s_h[s2 * 8 + j]);
        uint4 u3 = __ldg(&s_h[s3 * 8 + j]);
        acc_add8(acc, u0);
        acc_add8(acc, u1);
        acc_add8(acc, u2);
        acc_add8(acc, u3);
    }
    for (; k < end; k++) {
        int s = __ldg(&g_srcsort[k]);
        acc_add8(acc, __ldg(&s_h[s * 8 + j]));
    }

    float dv = __ldg(&s_dinv[v]);
    const float4* b4 = (const float4*)b;
    float4 bb0 = __ldg(&b4[j * 2 + 0]);
    float4 bb1 = __ldg(&b4[j * 2 + 1]);
    float o[8];
    o[0] = fmaxf(fmaf(acc[0], dv, bb0.x), 0.f);
    o[1] = fmaxf(fmaf(acc[1], dv, bb0.y), 0.f);
    o[2] = fmaxf(fmaf(acc[2], dv, bb0.z), 0.f);
    o[3] = fmaxf(fmaf(acc[3], dv, bb0.w), 0.f);
    o[4] = fmaxf(fmaf(acc[4], dv, bb1.x), 0.f);
    o[5] = fmaxf(fmaf(acc[5], dv, bb1.y), 0.f);
    o[6] = fmaxf(fmaf(acc[6], dv, bb1.z), 0.f);
    o[7] = fmaxf(fmaf(acc[7], dv, bb1.w), 0.f);

    if (OUT_HALF) {
        __half2 p0 = __floats2half2_rn(o[0], o[1]);
        __half2 p1 = __floats2half2_rn(o[2], o[3]);
        __half2 p2 = __floats2half2_rn(o[4], o[5]);
        __half2 p3 = __floats2half2_rn(o[6], o[7]);
        uint4 u;
        u.x = *(unsigned int*)&p0;
        u.y = *(unsigned int*)&p1;
        u.z = *(unsigned int*)&p2;
        u.w = *(unsigned int*)&p3;
        ((uint4*)out)[v * 8 + j] = u;
    } else {
        float4* O4 = (float4*)out;
        O4[v * 16 + j * 2 + 0] = make_float4(o[0], o[1], o[2], o[3]);
        O4[v * 16 + j * 2 + 1] = make_float4(o[4], o[5], o[6], o[7]);
    }
}

// ---------------------------------------------------------------------------
extern "C" void kernel_launch(void* const* d_in, const int* in_sizes, int n_in,
                              void* d_out, int out_size)
{
    const float* x  = (const float*)d_in[0];
    const int*   ei = (const int*)d_in[1];      // int32 (JAX x64 disabled)
    const float* W1 = (const float*)d_in[2];
    const float* b1 = (const float*)d_in[3];
    const float* W2 = (const float*)d_in[4];
    const float* b2 = (const float*)d_in[5];

    const int n = in_sizes[0] / D;        // 100000
    const int E = in_sizes[1] / 2;        // 1000000

    const int nb_e    = (E + 255) / 256;                   // sort blocks needed
    const int nb_sc   = (n + SCAN_B - 1) / SCAN_B;
    const int nb_gmm  = (n + TILE_ROWS - 1) / TILE_ROWS;   // gemm2 tiles
    const int nb_gmm1 = (n + TR2 - 1) / TR2;               // gemm1 tiles
    const int nb_agg  = (n * 8 + 255) / 256;               // 8 threads/node
    const int R       = (nb_e + nb_gmm1 - 1) / nb_gmm1;    // sort : gemm ratio

    // zero degree counters via a graph memset node
    void* degp = nullptr;
    cudaGetSymbolAddress(&degp, g_deg);
    cudaMemsetAsync(degp, 0, (size_t)n * sizeof(int));

    void* yh = nullptr;
    cudaGetSymbolAddress(&yh, s_yh);

    // --- graph preprocessing ---
    hist_kernel<<<nb_e, 256>>>(ei, E);
    scan_local_kernel<<<nb_sc, SCAN_B>>>(n);
    scan_add_fused_kernel<<<nb_sc, SCAN_B>>>(n, E, nb_sc);

    // sort truly interleaved with GEMM1 (R sort : 1 gemm per group, per wave)
    sort_gemm1_kernel<<<nb_gmm1 * (R + 1), 256>>>(x, W1, ei, n, E, R);

    // layer 1 aggregation -> fp16 y
    aggregate_kernel<true><<<nb_agg, 256>>>(b1, yh, n);

    // layer 2
    gemm2_kernel<<<nb_gmm, 256>>>(W2, n);
    aggregate_kernel<false><<<nb_agg, 256>>>(b2, d_out, n);
}

// round 15
// speedup vs baseline: 1.4693x; 1.2873x over previous
#include <cuda_runtime.h>
#include <cuda_fp16.h>
#include <cstdint>

#define N_MAX 100000
#define E_MAX 1000000
#define D 64
#define TILE_ROWS 128
#define SCAN_B 1024
#define XS_STRIDE 36        // u32 per xs row (144B) -> bank = 4g+tg, conflict-free
#define WT_STRIDE 36        // u32 per wt row

// Scratch (static device globals — no allocations allowed)
__device__ int    g_deg     [N_MAX];
__device__ int    g_rowptr  [N_MAX + 1];
__device__ int    g_cursor  [N_MAX];
__device__ int    g_srcsort [E_MAX];
__device__ int    g_bsums   [128];
__device__ float  s_dinv    [N_MAX];
__device__ uint4  s_h       [N_MAX * 8];    // fp16 gather source: 64 halves/row
__device__ uint4  s_yh      [N_MAX * 8];    // layer-1 output, fp16

// ---------------------------------------------------------------------------
// edge_index is INT32 on device (JAX x64 disabled canonicalizes int64->int32).
__global__ void hist_kernel(const int* __restrict__ ei, int E) {
    int e = blockIdx.x * blockDim.x + threadIdx.x;
    if (e < E) atomicAdd(&g_deg[ei[E + e]], 1);
}

// exclusive scan, stage 1: shuffle-based per-block scan + block totals
__global__ __launch_bounds__(SCAN_B) void scan_local_kernel(int n) {
    __shared__ int wsums[32];
    int t = threadIdx.x, lane = t & 31, w = t >> 5;
    int i = blockIdx.x * SCAN_B + t;
    int orig = (i < n) ? g_deg[i] : 0;
    int v = orig;
    #pragma unroll
    for (int o = 1; o < 32; o <<= 1) {
        int u = __shfl_up_sync(0xffffffffu, v, o);
        if (lane >= o) v += u;
    }
    if (lane == 31) wsums[w] = v;
    __syncthreads();
    if (w == 0) {
        int s = wsums[lane];
        #pragma unroll
        for (int o = 1; o < 32; o <<= 1) {
            int u = __shfl_up_sync(0xffffffffu, s, o);
            if (lane >= o) s += u;
        }
        wsums[lane] = s;
    }
    __syncthreads();
    int incl = v + ((w > 0) ? wsums[w - 1] : 0);
    if (i < n) g_rowptr[i] = incl - orig;             // exclusive
    if (t == SCAN_B - 1) g_bsums[blockIdx.x] = incl;  // block total
}

// stage 2 (fused): per-block redundant reduction of lower block sums; dinv; cursors.
__global__ __launch_bounds__(SCAN_B) void scan_add_fused_kernel(int n, int E, int nb) {
    __shared__ int sh[128];
    __shared__ int offset;
    int t = threadIdx.x;
    if (t < 128) sh[t] = (t < nb && t < (int)blockIdx.x) ? g_bsums[t] : 0;
    __syncthreads();
    if (t < 64) sh[t] += sh[t + 64];
    __syncthreads();
    if (t < 32) {
        int v = sh[t] + sh[t + 32];
        #pragma unroll
        for (int o = 16; o > 0; o >>= 1) v += __shfl_down_sync(0xffffffffu, v, o);
        if (t == 0) offset = v;
    }
    __syncthreads();
    int i = blockIdx.x * SCAN_B + t;
    if (i < n) {
        int r = g_rowptr[i] + offset;
        g_rowptr[i] = r;
        g_cursor[i] = r;
        s_dinv[i] = rsqrtf((float)g_deg[i] + 1.0f);   // +1 self loop
    }
    if (i == 0) g_rowptr[n] = E;
}

// counting-sort scatter, scalar form (16 regs, 0 smem, 77% occ — proven 17.4us)
__global__ void sort_kernel(const int* __restrict__ ei, int E) {
    int e = blockIdx.x * blockDim.x + threadIdx.x;
    if (e < E) {
        int src = ei[e];
        int dst = ei[E + e];
        int pos = atomicAdd(&g_cursor[dst], 1);
        g_srcsort[pos] = src;
    }
}

// ---------------------------------------------------------------------------
// Tensor-core GEMM: h = dinv * (X @ W), fp16 store to s_h.
// mma.sync m16n8k16 f32.f16.f16.f32. 256 threads = 8 warps; warp computes
// 16 rows x 64 cols (4 k-chunks x 8 n-blocks). W transposed to [n][k] fp16
// in smem. IN_HALF: input fp16 (s_yh); else fp32 converted on tile load.
template <bool IN_HALF>
__device__ __forceinline__ void gemm_mma_body(
    const void* __restrict__ Xv, const float* __restrict__ W,
    int n, int row0, uint32_t* xs, uint32_t* wt)
{
    const int tid = threadIdx.x;

    // W (64x64 fp32, [k][n] row-major) -> wt fp16 [n][k], row stride 72 halves
    __half* wt_h = (__half*)wt;
    #pragma unroll
    for (int i = tid; i < D * D; i += 256) {
        int k = i >> 6, nn = i & 63;
        wt_h[nn * (WT_STRIDE * 2) + k] = __float2half(__ldg(&W[i]));
    }

    // X tile -> xs fp16, 128 rows x 32 u32 (stride XS_STRIDE)
    #pragma unroll
    for (int i = tid; i < TILE_ROWS * 32; i += 256) {
        int r = i >> 5, c = i & 31;
        uint32_t u = 0u;
        if (row0 + r < n) {
            if (IN_HALF) {
                u = __ldg(&((const uint32_t*)Xv)[(row0 + r) * 32 + c]);
            } else {
                float2 v = __ldg(&((const float2*)Xv)[(row0 + r) * 32 + c]);
                __half2 p = __floats2half2_rn(v.x, v.y);
                u = *(uint32_t*)&p;
            }
        }
        xs[r * XS_STRIDE + c] = u;
    }
    __syncthreads();

    const int warp = tid >> 5, lane = tid & 31;
    const int g = lane >> 2, tg = lane & 3;
    const int r_lo = warp * 16 + g;            // local row (0..127)

    float c[8][4];
    #pragma unroll
    for (int nb = 0; nb < 8; nb++)
        #pragma unroll
        for (int q = 0; q < 4; q++) c[nb][q] = 0.f;

    const uint32_t* xlo = xs + r_lo * XS_STRIDE;
    const uint32_t* xhi = xs + (r_lo + 8) * XS_STRIDE;

    #pragma unroll
    for (int kc = 0; kc < 4; kc++) {
        uint32_t a0 = xlo[kc * 8 + tg];        // row g,   k 0..7
        uint32_t a1 = xhi[kc * 8 + tg];        // row g+8, k 0..7
        uint32_t a2 = xlo[kc * 8 + 4 + tg];    // row g,   k 8..15
        uint32_t a3 = xhi[kc * 8 + 4 + tg];    // row g+8, k 8..15
        #pragma unroll
        for (int nb = 0; nb < 8; nb++) {
            int nn = nb * 8 + g;
            uint32_t b0 = wt[nn * WT_STRIDE + kc * 8 + tg];
            uint32_t b1 = wt[nn * WT_STRIDE + kc * 8 + 4 + tg];
            asm volatile(
                "mma.sync.aligned.m16n8k16.row.col.f32.f16.f16.f32 "
                "{%0,%1,%2,%3}, {%4,%5,%6,%7}, {%8,%9}, {%0,%1,%2,%3};"
                : "+f"(c[nb][0]), "+f"(c[nb][1]), "+f"(c[nb][2]), "+f"(c[nb][3])
                : "r"(a0), "r"(a1), "r"(a2), "r"(a3), "r"(b0), "r"(b1));
        }
    }

    // epilogue: scale by dinv, pack fp16, store to s_h
    int grow_lo = row0 + r_lo, grow_hi = grow_lo + 8;
    float dlo = (grow_lo < n) ? s_dinv[grow_lo] : 0.f;
    float dhi = (grow_hi < n) ? s_dinv[grow_hi] : 0.f;
    uint32_t* H = (uint32_t*)s_h;
    #pragma unroll
    for (int nb = 0; nb < 8; nb++) {
        if (grow_lo < n) {
            __half2 p = __floats2half2_rn(c[nb][0] * dlo, c[nb][1] * dlo);
            H[grow_lo * 32 + nb * 4 + tg] = *(uint32_t*)&p;
        }
        if (grow_hi < n) {
            __half2 p = __floats2half2_rn(c[nb][2] * dhi, c[nb][3] * dhi);
            H[grow_hi * 32 + nb * 4 + tg] = *(uint32_t*)&p;
        }
    }
}

__global__ __launch_bounds__(256) void gemm1_kernel(
    const float* __restrict__ X, const float* __restrict__ W, int n)
{
    __shared__ uint32_t xs[TILE_ROWS * XS_STRIDE];   // 18.4KB
    __shared__ uint32_t wt[D * WT_STRIDE];           // 9.2KB
    gemm_mma_body<false>(X, W, n, blockIdx.x * TILE_ROWS, xs, wt);
}

__global__ __launch_bounds__(256) void gemm2_kernel(
    const float* __restrict__ W, int n)
{
    __shared__ uint32_t xs[TILE_ROWS * XS_STRIDE];
    __shared__ uint32_t wt[D * WT_STRIDE];
    gemm_mma_body<true>(s_yh, W, n, blockIdx.x * TILE_ROWS, xs, wt);
}

// ---------------------------------------------------------------------------
__device__ __forceinline__ void acc_add8(float acc[8], uint4 u) {
    float2 f0 = __half22float2(*(__half2*)&u.x);
    float2 f1 = __half22float2(*(__half2*)&u.y);
    float2 f2 = __half22float2(*(__half2*)&u.z);
    float2 f3 = __half22float2(*(__half2*)&u.w);
    acc[0] += f0.x; acc[1] += f0.y; acc[2] += f1.x; acc[3] += f1.y;
    acc[4] += f2.x; acc[5] += f2.y; acc[6] += f3.x; acc[7] += f3.y;
}

// Gather-aggregate + epilogue (R11-proven). 8 threads/node, one uint4 each,
// batch-4 index loads for MLP. OUT_HALF: fp16 out (layer 1); else fp32.
template <bool OUT_HALF>
__global__ __launch_bounds__(256) void aggregate_kernel(
    const float* __restrict__ b, void* __restrict__ out, int n)
{
    int idx = blockIdx.x * blockDim.x + threadIdx.x;
    int v = idx >> 3;
    if (v >= n) return;
    int j = idx & 7;

    float acc[8];
    #pragma unroll
    for (int c = 0; c < 8; c++) acc[c] = 0.f;
    acc_add8(acc, __ldg(&s_h[v * 8 + j]));             // self loop

    int beg = __ldg(&g_rowptr[v]);
    int end = __ldg(&g_rowptr[v + 1]);

    int k = beg;
    #pragma unroll 1
    for (; k + 4 <= end; k += 4) {
        int s0 = __ldg(&g_srcsort[k + 0]);
        int s1 = __ldg(&g_srcsort[k + 1]);
        int s2 = __ldg(&g_srcsort[k + 2]);
        int s3 = __ldg(&g_srcsort[k + 3]);
        uint4 u0 = __ldg(&s_h[s0 * 8 + j]);
        uint4 u1 = __ldg(&s_h[s1 * 8 + j]);
        uint4 u2 = __ldg(&s_h[s2 * 8 + j]);
        uint4 u3 = __ldg(&s_h[s3 * 8 + j]);
        acc_add8(acc, u0);
        acc_add8(acc, u1);
        acc_add8(acc, u2);
        acc_add8(acc, u3);
    }
    for (; k < end; k++) {
        int s = __ldg(&g_srcsort[k]);
        acc_add8(acc, __ldg(&s_h[s * 8 + j]));
    }

    float dv = __ldg(&s_dinv[v]);
    const float4* b4 = (const float4*)b;
    float4 bb0 = __ldg(&b4[j * 2 + 0]);
    float4 bb1 = __ldg(&b4[j * 2 + 1]);
    float o[8];
    o[0] = fmaxf(fmaf(acc[0], dv, bb0.x), 0.f);
    o[1] = fmaxf(fmaf(acc[1], dv, bb0.y), 0.f);
    o[2] = fmaxf(fmaf(acc[2], dv, bb0.z), 0.f);
    o[3] = fmaxf(fmaf(acc[3], dv, bb0.w), 0.f);
    o[4] = fmaxf(fmaf(acc[4], dv, bb1.x), 0.f);
    o[5] = fmaxf(fmaf(acc[5], dv, bb1.y), 0.f);
    o[6] = fmaxf(fmaf(acc[6], dv, bb1.z), 0.f);
    o[7] = fmaxf(fmaf(acc[7], dv, bb1.w), 0.f);

    if (OUT_HALF) {
        __half2 p0 = __floats2half2_rn(o[0], o[1]);
        __half2 p1 = __floats2half2_rn(o[2], o[3]);
        __half2 p2 = __floats2half2_rn(o[4], o[5]);
        __half2 p3 = __floats2half2_rn(o[6], o[7]);
        uint4 u;
        u.x = *(unsigned int*)&p0;
        u.y = *(unsigned int*)&p1;
        u.z = *(unsigned int*)&p2;
        u.w = *(unsigned int*)&p3;
        ((uint4*)out)[v * 8 + j] = u;
    } else {
        float4* O4 = (float4*)out;
        O4[v * 16 + j * 2 + 0] = make_float4(o[0], o[1], o[2], o[3]);
        O4[v * 16 + j * 2 + 1] = make_float4(o[4], o[5], o[6], o[7]);
    }
}

// ---------------------------------------------------------------------------
extern "C" void kernel_launch(void* const* d_in, const int* in_sizes, int n_in,
                              void* d_out, int out_size)
{
    const float* x  = (const float*)d_in[0];
    const int*   ei = (const int*)d_in[1];      // int32 (JAX x64 disabled)
    const float* W1 = (const float*)d_in[2];
    const float* b1 = (const float*)d_in[3];
    const float* W2 = (const float*)d_in[4];
    const float* b2 = (const float*)d_in[5];

    const int n = in_sizes[0] / D;        // 100000
    const int E = in_sizes[1] / 2;        // 1000000

    const int nb_e   = (E + 255) / 256;
    const int nb_sc  = (n + SCAN_B - 1) / SCAN_B;
    const int nb_gmm = (n + TILE_ROWS - 1) / TILE_ROWS;
    const int nb_agg = (n * 8 + 255) / 256;

    // zero degree counters via a graph memset node
    void* degp = nullptr;
    cudaGetSymbolAddress(&degp, g_deg);
    cudaMemsetAsync(degp, 0, (size_t)n * sizeof(int));

    void* yh = nullptr;
    cudaGetSymbolAddress(&yh, s_yh);

    // --- graph preprocessing ---
    hist_kernel<<<nb_e, 256>>>(ei, E);
    scan_local_kernel<<<nb_sc, SCAN_B>>>(n);
    scan_add_fused_kernel<<<nb_sc, SCAN_B>>>(n, E, nb_sc);
    sort_kernel<<<nb_e, 256>>>(ei, E);

    // layer 1 (tensor-core GEMM)
    gemm1_kernel<<<nb_gmm, 256>>>(x, W1, n);
    aggregate_kernel<true><<<nb_agg, 256>>>(b1, yh, n);

    // layer 2
    gemm2_kernel<<<nb_gmm, 256>>>(W2, n);
    aggregate_kernel<false><<<nb_agg, 256>>>(b2, d_out, n);
}

// round 16
// speedup vs baseline: 1.4776x; 1.0057x over previous
#include <cuda_runtime.h>
#include <cuda_fp16.h>
#include <cstdint>

#define N_MAX 100000
#define E_MAX 1000000
#define D 64
#define TILE_ROWS 128
#define SCAN_B 1024
#define XS_STRIDE 36        // u32 per xs row (144B) -> bank = 4g+tg, conflict-free
#define WT_STRIDE 36        // u32 per wt row

// Scratch (static device globals — no allocations allowed)
__device__ int    g_deg     [N_MAX];
__device__ int    g_rowptr  [N_MAX + 1];
__device__ int    g_rank    [E_MAX];        // per-edge rank within dst bucket
__device__ int    g_srcsort [E_MAX];
__device__ int    g_bsums   [128];
__device__ float  s_dinv    [N_MAX];
__device__ uint4  s_h       [N_MAX * 8];    // fp16 gather source: 64 halves/row
__device__ uint4  s_yh      [N_MAX * 8];    // layer-1 output, fp16

// ---------------------------------------------------------------------------
// edge_index is INT32 on device (JAX x64 disabled canonicalizes int64->int32).
// Histogram WITH returned rank: the atomic we already paid for also yields
// each edge's position within its dst bucket -> the placement pass below
// needs NO atomics at all.
__global__ void hist_rank_kernel(const int* __restrict__ ei, int E) {
    int e = blockIdx.x * blockDim.x + threadIdx.x;
    if (e < E) g_rank[e] = atomicAdd(&g_deg[ei[E + e]], 1);
}

// exclusive scan, stage 1: shuffle-based per-block scan + block totals
__global__ __launch_bounds__(SCAN_B) void scan_local_kernel(int n) {
    __shared__ int wsums[32];
    int t = threadIdx.x, lane = t & 31, w = t >> 5;
    int i = blockIdx.x * SCAN_B + t;
    int orig = (i < n) ? g_deg[i] : 0;
    int v = orig;
    #pragma unroll
    for (int o = 1; o < 32; o <<= 1) {
        int u = __shfl_up_sync(0xffffffffu, v, o);
        if (lane >= o) v += u;
    }
    if (lane == 31) wsums[w] = v;
    __syncthreads();
    if (w == 0) {
        int s = wsums[lane];
        #pragma unroll
        for (int o = 1; o < 32; o <<= 1) {
            int u = __shfl_up_sync(0xffffffffu, s, o);
            if (lane >= o) s += u;
        }
        wsums[lane] = s;
    }
    __syncthreads();
    int incl = v + ((w > 0) ? wsums[w - 1] : 0);
    if (i < n) g_rowptr[i] = incl - orig;             // exclusive
    if (t == SCAN_B - 1) g_bsums[blockIdx.x] = incl;  // block total
}

// stage 2 (fused): per-block redundant reduction of lower block sums; dinv.
__global__ __launch_bounds__(SCAN_B) void scan_add_fused_kernel(int n, int E, int nb) {
    __shared__ int sh[128];
    __shared__ int offset;
    int t = threadIdx.x;
    if (t < 128) sh[t] = (t < nb && t < (int)blockIdx.x) ? g_bsums[t] : 0;
    __syncthreads();
    if (t < 64) sh[t] += sh[t + 64];
    __syncthreads();
    if (t < 32) {
        int v = sh[t] + sh[t + 32];
        #pragma unroll
        for (int o = 16; o > 0; o >>= 1) v += __shfl_down_sync(0xffffffffu, v, o);
        if (t == 0) offset = v;
    }
    __syncthreads();
    int i = blockIdx.x * SCAN_B + t;
    if (i < n) {
        g_rowptr[i] += offset;
        s_dinv[i] = rsqrtf((float)g_deg[i] + 1.0f);   // +1 self loop
    }
    if (i == 0) g_rowptr[n] = E;
}

// atomic-free placement: pos = rowptr[dst] + rank[e]
__global__ void place_kernel(const int* __restrict__ ei, int E) {
    int e = blockIdx.x * blockDim.x + threadIdx.x;
    if (e < E) {
        int src = __ldg(&ei[e]);
        int dst = __ldg(&ei[E + e]);
        int pos = __ldg(&g_rowptr[dst]) + g_rank[e];
        g_srcsort[pos] = src;
    }
}

// ---------------------------------------------------------------------------
// Tensor-core GEMM: h = dinv * (X @ W), fp16 store to s_h.
// mma.sync m16n8k16 f32.f16.f16.f32. 256 threads = 8 warps; warp computes
// 16 rows x 64 cols (4 k-chunks x 8 n-blocks). W transposed to [n][k] fp16
// in smem. IN_HALF: input fp16 (s_yh); else fp32 converted on tile load.
template <bool IN_HALF>
__device__ __forceinline__ void gemm_mma_body(
    const void* __restrict__ Xv, const float* __restrict__ W,
    int n, int row0, uint32_t* xs, uint32_t* wt)
{
    const int tid = threadIdx.x;

    // W (64x64 fp32, [k][n] row-major) -> wt fp16 [n][k], row stride 72 halves
    __half* wt_h = (__half*)wt;
    #pragma unroll
    for (int i = tid; i < D * D; i += 256) {
        int k = i >> 6, nn = i & 63;
        wt_h[nn * (WT_STRIDE * 2) + k] = __float2half(__ldg(&W[i]));
    }

    // X tile -> xs fp16, 128 rows x 32 u32 (stride XS_STRIDE)
    #pragma unroll
    for (int i = tid; i < TILE_ROWS * 32; i += 256) {
        int r = i >> 5, c = i & 31;
        uint32_t u = 0u;
        if (row0 + r < n) {
            if (IN_HALF) {
                u = __ldg(&((const uint32_t*)Xv)[(row0 + r) * 32 + c]);
            } else {
                float2 v = __ldg(&((const float2*)Xv)[(row0 + r) * 32 + c]);
                __half2 p = __floats2half2_rn(v.x, v.y);
                u = *(uint32_t*)&p;
            }
        }
        xs[r * XS_STRIDE + c] = u;
    }
    __syncthreads();

    const int warp = tid >> 5, lane = tid & 31;
    const int g = lane >> 2, tg = lane & 3;
    const int r_lo = warp * 16 + g;            // local row (0..127)

    float c[8][4];
    #pragma unroll
    for (int nb = 0; nb < 8; nb++)
        #pragma unroll
        for (int q = 0; q < 4; q++) c[nb][q] = 0.f;

    const uint32_t* xlo = xs + r_lo * XS_STRIDE;
    const uint32_t* xhi = xs + (r_lo + 8) * XS_STRIDE;

    #pragma unroll
    for (int kc = 0; kc < 4; kc++) {
        uint32_t a0 = xlo[kc * 8 + tg];        // row g,   k 0..7
        uint32_t a1 = xhi[kc * 8 + tg];        // row g+8, k 0..7
        uint32_t a2 = xlo[kc * 8 + 4 + tg];    // row g,   k 8..15
        uint32_t a3 = xhi[kc * 8 + 4 + tg];    // row g+8, k 8..15
        #pragma unroll
        for (int nb = 0; nb < 8; nb++) {
            int nn = nb * 8 + g;
            uint32_t b0 = wt[nn * WT_STRIDE + kc * 8 + tg];
            uint32_t b1 = wt[nn * WT_STRIDE + kc * 8 + 4 + tg];
            asm volatile(
                "mma.sync.aligned.m16n8k16.row.col.f32.f16.f16.f32 "
                "{%0,%1,%2,%3}, {%4,%5,%6,%7}, {%8,%9}, {%0,%1,%2,%3};"
                : "+f"(c[nb][0]), "+f"(c[nb][1]), "+f"(c[nb][2]), "+f"(c[nb][3])
                : "r"(a0), "r"(a1), "r"(a2), "r"(a3), "r"(b0), "r"(b1));
        }
    }

    // epilogue: scale by dinv, pack fp16, store to s_h
    int grow_lo = row0 + r_lo, grow_hi = grow_lo + 8;
    float dlo = (grow_lo < n) ? s_dinv[grow_lo] : 0.f;
    float dhi = (grow_hi < n) ? s_dinv[grow_hi] : 0.f;
    uint32_t* H = (uint32_t*)s_h;
    #pragma unroll
    for (int nb = 0; nb < 8; nb++) {
        if (grow_lo < n) {
            __half2 p = __floats2half2_rn(c[nb][0] * dlo, c[nb][1] * dlo);
            H[grow_lo * 32 + nb * 4 + tg] = *(uint32_t*)&p;
        }
        if (grow_hi < n) {
            __half2 p = __floats2half2_rn(c[nb][2] * dhi, c[nb][3] * dhi);
            H[grow_hi * 32 + nb * 4 + tg] = *(uint32_t*)&p;
        }
    }
}

__global__ __launch_bounds__(256) void gemm1_kernel(
    const float* __restrict__ X, const float* __restrict__ W, int n)
{
    __shared__ uint32_t xs[TILE_ROWS * XS_STRIDE];   // 18.4KB
    __shared__ uint32_t wt[D * WT_STRIDE];           // 9.2KB
    gemm_mma_body<false>(X, W, n, blockIdx.x * TILE_ROWS, xs, wt);
}

__global__ __launch_bounds__(256) void gemm2_kernel(
    const float* __restrict__ W, int n)
{
    __shared__ uint32_t xs[TILE_ROWS * XS_STRIDE];
    __shared__ uint32_t wt[D * WT_STRIDE];
    gemm_mma_body<true>(s_yh, W, n, blockIdx.x * TILE_ROWS, xs, wt);
}

// ---------------------------------------------------------------------------
__device__ __forceinline__ void acc_add8(float acc[8], uint4 u) {
    float2 f0 = __half22float2(*(__half2*)&u.x);
    float2 f1 = __half22float2(*(__half2*)&u.y);
    float2 f2 = __half22float2(*(__half2*)&u.z);
    float2 f3 = __half22float2(*(__half2*)&u.w);
    acc[0] += f0.x; acc[1] += f0.y; acc[2] += f1.x; acc[3] += f1.y;
    acc[4] += f2.x; acc[5] += f2.y; acc[6] += f3.x; acc[7] += f3.y;
}

// Gather-aggregate + epilogue (R11-proven). 8 threads/node, one uint4 each,
// batch-4 index loads for MLP. OUT_HALF: fp16 out (layer 1); else fp32.
template <bool OUT_HALF>
__global__ __launch_bounds__(256) void aggregate_kernel(
    const float* __restrict__ b, void* __restrict__ out, int n)
{
    int idx = blockIdx.x * blockDim.x + threadIdx.x;
    int v = idx >> 3;
    if (v >= n) return;
    int j = idx & 7;

    float acc[8];
    #pragma unroll
    for (int c = 0; c < 8; c++) acc[c] = 0.f;
    acc_add8(acc, __ldg(&s_h[v * 8 + j]));             // self loop

    int beg = __ldg(&g_rowptr[v]);
    int end = __ldg(&g_rowptr[v + 1]);

    int k = beg;
    #pragma unroll 1
    for (; k + 4 <= end; k += 4) {
        int s0 = __ldg(&g_srcsort[k + 0]);
        int s1 = __ldg(&g_srcsort[k + 1]);
        int s2 = __ldg(&g_srcsort[k + 2]);
        int s3 = __ldg(&g_srcsort[k + 3]);
        uint4 u0 = __ldg(&s_h[s0 * 8 + j]);
        uint4 u1 = __ldg(&s_h[s1 * 8 + j]);
        uint4 u2 = __ldg(&s_h[s2 * 8 + j]);
        uint4 u3 = __ldg(&s_h[s3 * 8 + j]);
        acc_add8(acc, u0);
        acc_add8(acc, u1);
        acc_add8(acc, u2);
        acc_add8(acc, u3);
    }
    for (; k < end; k++) {
        int s = __ldg(&g_srcsort[k]);
        acc_add8(acc, __ldg(&s_h[s * 8 + j]));
    }

    float dv = __ldg(&s_dinv[v]);
    const float4* b4 = (const float4*)b;
    float4 bb0 = __ldg(&b4[j * 2 + 0]);
    float4 bb1 = __ldg(&b4[j * 2 + 1]);
    float o[8];
    o[0] = fmaxf(fmaf(acc[0], dv, bb0.x), 0.f);
    o[1] = fmaxf(fmaf(acc[1], dv, bb0.y), 0.f);
    o[2] = fmaxf(fmaf(acc[2], dv, bb0.z), 0.f);
    o[3] = fmaxf(fmaf(acc[3], dv, bb0.w), 0.f);
    o[4] = fmaxf(fmaf(acc[4], dv, bb1.x), 0.f);
    o[5] = fmaxf(fmaf(acc[5], dv, bb1.y), 0.f);
    o[6] = fmaxf(fmaf(acc[6], dv, bb1.z), 0.f);
    o[7] = fmaxf(fmaf(acc[7], dv, bb1.w), 0.f);

    if (OUT_HALF) {
        __half2 p0 = __floats2half2_rn(o[0], o[1]);
        __half2 p1 = __floats2half2_rn(o[2], o[3]);
        __half2 p2 = __floats2half2_rn(o[4], o[5]);
        __half2 p3 = __floats2half2_rn(o[6], o[7]);
        uint4 u;
        u.x = *(unsigned int*)&p0;
        u.y = *(unsigned int*)&p1;
        u.z = *(unsigned int*)&p2;
        u.w = *(unsigned int*)&p3;
        ((uint4*)out)[v * 8 + j] = u;
    } else {
        float4* O4 = (float4*)out;
        O4[v * 16 + j * 2 + 0] = make_float4(o[0], o[1], o[2], o[3]);
        O4[v * 16 + j * 2 + 1] = make_float4(o[4], o[5], o[6], o[7]);
    }
}

// ---------------------------------------------------------------------------
extern "C" void kernel_launch(void* const* d_in, const int* in_sizes, int n_in,
                              void* d_out, int out_size)
{
    const float* x  = (const float*)d_in[0];
    const int*   ei = (const int*)d_in[1];      // int32 (JAX x64 disabled)
    const float* W1 = (const float*)d_in[2];
    const float* b1 = (const float*)d_in[3];
    const float* W2 = (const float*)d_in[4];
    const float* b2 = (const float*)d_in[5];

    const int n = in_sizes[0] / D;        // 100000
    const int E = in_sizes[1] / 2;        // 1000000

    const int nb_e   = (E + 255) / 256;
    const int nb_sc  = (n + SCAN_B - 1) / SCAN_B;
    const int nb_gmm = (n + TILE_ROWS - 1) / TILE_ROWS;
    const int nb_agg = (n * 8 + 255) / 256;

    // zero degree counters via a graph memset node
    void* degp = nullptr;
    cudaGetSymbolAddress(&degp, g_deg);
    cudaMemsetAsync(degp, 0, (size_t)n * sizeof(int));

    void* yh = nullptr;
    cudaGetSymbolAddress(&yh, s_yh);

    // --- graph preprocessing (rank-based, atomic-free placement) ---
    hist_rank_kernel<<<nb_e, 256>>>(ei, E);
    scan_local_kernel<<<nb_sc, SCAN_B>>>(n);
    scan_add_fused_kernel<<<nb_sc, SCAN_B>>>(n, E, nb_sc);
    place_kernel<<<nb_e, 256>>>(ei, E);

    // layer 1 (tensor-core GEMM)
    gemm1_kernel<<<nb_gmm, 256>>>(x, W1, n);
    aggregate_kernel<true><<<nb_agg, 256>>>(b1, yh, n);

    // layer 2
    gemm2_kernel<<<nb_gmm, 256>>>(W2, n);
    aggregate_kernel<false><<<nb_agg, 256>>>(b2, d_out, n);
}